// round 4
// baseline (speedup 1.0000x reference)
#include <cuda_runtime.h>
#include <cuda_bf16.h>
#include <cstdint>

#define Bq 4
#define NF 5
#define HSq 512
#define Sq 1024

#define XF(ff,jj,ii) xb[((size_t)(ff)*HSq + (jj))*Sq + (ii)]

// Boundary point: ports the reference's 12 perimeter cases for one (j,i).
__device__ __forceinline__ void bpoint(
    const float* __restrict__ xb, const float* __restrict__ poles,
    const float* __restrict__ we,   const float* __restrict__ wcn,
    const float* __restrict__ wne,  const float* __restrict__ wnne,
    const float* __restrict__ wnw,  const float* __restrict__ wnww,
    const float* __restrict__ wwe,  const float* __restrict__ wsw,
    const float* __restrict__ wsse, const float* __restrict__ wse,
    const float* __restrict__ wcs,
    int b, int f, int pf, int nf2, int j, int i,
    float& c0, float& c1, float& c2, float& c3)
{
    if (j == 0) {
        float ctr = XF(f, 0, i);
        if (i == 0) {
            c0 = (XF(pf, HSq - 1, HSq - 1) - ctr) * wcs[0];
            c1 = (XF(f, 1, 1) - ctr) * wcs[1];
            c2 = (XF(pf, HSq - 1, HSq) - ctr) * wcs[2] + (XF(f, 0, 1) - ctr) * wcs[3];
            c3 = (XF(f, 1, 0) - ctr) * wcs[4];
        } else if (i <= HSq - 1) {
            int k = i - 1; const int W = HSq - 1;
            c0 = (XF(pf, HSq - 1, HSq + k) - ctr) * we[k];
            c1 = (XF(f, 1, i + 1) - ctr) * we[W + k];
            c2 = (XF(pf, HSq - 1, HSq + 1 + k) - ctr) * we[2 * W + k]
               + (XF(f, 0, i + 1) - ctr) * we[3 * W + k];
            c3 = (XF(f, 0, i - 1) - ctr) * we[4 * W + k]
               + (XF(f, 1, i) - ctr) * we[5 * W + k];
        } else if (i == HSq) {
            c0 = (XF(pf, HSq - 1, Sq - 1) - ctr) * wcn[0];
            c1 = (XF(f, 1, HSq + 1) - ctr) * wcn[1];
            c2 = (XF(f, 0, HSq + 1) - ctr) * wcn[2];
            c3 = (XF(f, 0, HSq - 1) - ctr) * wcn[3] + (XF(f, 1, HSq) - ctr) * wcn[4];
        } else if (i <= Sq - 2) {
            int k = i - (HSq + 1); const int W = HSq - 2;
            c0 = (XF(pf, HSq - 2 - k, Sq - 1) - ctr) * wne[k]
               + (XF(pf, HSq - 1 - k, Sq - 1) - ctr) * wne[W + k];
            c1 = (XF(f, 1, i + 1) - ctr) * wne[2 * W + k]
               + (XF(f, 1, i) - ctr) * wne[3 * W + k];
            c2 = (XF(f, 0, i + 1) - ctr) * wne[4 * W + k];
            c3 = (XF(f, 0, i - 1) - ctr) * wne[5 * W + k];
        } else {
            c0 = (XF(pf, 0, Sq - 1) - ctr) * wnne[0] + (XF(pf, 1, Sq - 1) - ctr) * wnne[1];
            c1 = (XF(nf2, 0, Sq - 1) - ctr) * wnne[2] + (XF(f, 1, Sq - 1) - ctr) * wnne[3];
            c2 = (poles[b * 2 + 1] - ctr) * wnne[4];
            c3 = (XF(f, 0, Sq - 2) - ctr) * wnne[5];
        }
    } else if (j == HSq - 1) {
        float ctr = XF(f, HSq - 1, i);
        if (i == 0) {
            c0 = (XF(pf, HSq - 1, 0) - ctr) * wsse[0];
            c1 = (XF(nf2, HSq - 1, 0) - ctr) * wsse[1];
            c2 = (XF(f, HSq - 2, 0) - ctr) * wsse[2] + (XF(f, HSq - 1, 1) - ctr) * wsse[3];
            c3 = (poles[b * 2 + 0] - ctr) * wsse[4];
        } else if (i <= HSq - 1) {
            int k = i - 1; const int W = HSq - 1;
            c0 = (XF(f, HSq - 2, i - 1) - ctr) * wsw[k];
            c1 = (XF(nf2, HSq - 2 - k, 0) - ctr) * wsw[W + k];
            c2 = (XF(f, HSq - 2, i) - ctr) * wsw[2 * W + k]
               + (XF(f, HSq - 1, i + 1) - ctr) * wsw[3 * W + k];
            c3 = (XF(f, HSq - 1, i - 1) - ctr) * wsw[4 * W + k]
               + (XF(nf2, HSq - 1 - k, 0) - ctr) * wsw[5 * W + k];
        } else if (i <= Sq - 2) {
            int k = i - HSq; const int W = HSq - 1;
            c0 = (XF(f, HSq - 2, i - 1) - ctr) * wwe[k];
            c1 = (XF(nf2, 0, 1 + k) - ctr) * wwe[W + k];
            c2 = (XF(f, HSq - 2, i) - ctr) * wwe[2 * W + k]
               + (XF(f, HSq - 1, i + 1) - ctr) * wwe[3 * W + k];
            c3 = (XF(f, HSq - 1, i - 1) - ctr) * wwe[4 * W + k]
               + (XF(nf2, 0, k) - ctr) * wwe[5 * W + k];
        } else {
            c0 = (XF(f, HSq - 2, Sq - 2) - ctr) * wnww[0];
            c1 = (XF(nf2, 0, HSq) - ctr) * wnww[1];
            c2 = (XF(f, HSq - 2, Sq - 1) - ctr) * wnww[2]
               + (XF(nf2, 0, HSq + 1) - ctr) * wnww[3];
            c3 = (XF(f, HSq - 1, Sq - 2) - ctr) * wnww[4]
               + (XF(nf2, 0, HSq - 1) - ctr) * wnww[5];
        }
    } else if (i == 0) {
        int k = j - 1; const int W = HSq - 2;
        float ctr = XF(f, j, 0);
        c0 = (XF(pf, HSq - 1, HSq - 1 - k) - ctr) * wse[k]
           + (XF(pf, HSq - 1, HSq - 2 - k) - ctr) * wse[W + k];
        c1 = (XF(f, j, 1) - ctr) * wse[2 * W + k]
           + (XF(f, j + 1, 1) - ctr) * wse[3 * W + k];
        c2 = (XF(f, j - 1, 0) - ctr) * wse[4 * W + k];
        c3 = (XF(f, j + 1, 0) - ctr) * wse[5 * W + k];
    } else {
        int k = j - 1; const int W = HSq - 2;
        float ctr = XF(f, j, Sq - 1);
        c0 = (XF(f, j - 1, Sq - 2) - ctr) * wnw[k];
        c1 = (XF(nf2, 0, Sq - 2 - k) - ctr) * wnw[W + k];
        c2 = (XF(f, j - 1, Sq - 1) - ctr) * wnw[2 * W + k]
           + (XF(nf2, 0, Sq - 1 - k) - ctr) * wnw[3 * W + k];
        c3 = (XF(f, j, Sq - 2) - ctr) * wnw[4 * W + k]
           + (XF(f, j + 1, Sq - 1) - ctr) * wnw[5 * W + k];
    }
}

// Inner scalar point
__device__ __forceinline__ void ipoint(
    const float* __restrict__ xp, const float* __restrict__ wi,
    int j, int i, float& c0, float& c1, float& c2, float& c3)
{
    const int WP = (HSq - 2) * (Sq - 2);
    int k = (j - 1) * (Sq - 2) + (i - 1);
    float ctr = xp[(size_t)j * Sq + i];
    c0 = (xp[(size_t)(j - 1) * Sq + i - 1] - ctr) * wi[k];
    c1 = (xp[(size_t)(j + 1) * Sq + i + 1] - ctr) * wi[WP + k];
    c2 = (xp[(size_t)(j - 1) * Sq + i] - ctr) * wi[2 * WP + k]
       + (xp[(size_t)j * Sq + i + 1] - ctr) * wi[3 * WP + k];
    c3 = (xp[(size_t)j * Sq + i - 1] - ctr) * wi[4 * WP + k]
       + (xp[(size_t)(j + 1) * Sq + i] - ctr) * wi[5 * WP + k];
}

__global__ void __launch_bounds__(128) fused_kernel(
    const float* __restrict__ x,
    const float* __restrict__ poles,
    const float* __restrict__ wi,
    const float* __restrict__ we,   const float* __restrict__ wcn,
    const float* __restrict__ wne,  const float* __restrict__ wnne,
    const float* __restrict__ wnw,  const float* __restrict__ wnww,
    const float* __restrict__ wwe,  const float* __restrict__ wsw,
    const float* __restrict__ wsse, const float* __restrict__ wse,
    const float* __restrict__ wcs,
    float* __restrict__ out)
{
    const size_t FP  = (size_t)HSq * Sq;     // one face plane
    const size_t CP5 = (size_t)NF * FP;      // comp stride in out

    int c  = 2 * (blockIdx.x * 128 + threadIdx.x);   // 2 columns per thread
    int ty = blockIdx.y;
    int f  = blockIdx.z;
    int pf  = (f == 0) ? 4 : f - 1;
    int nf2 = (f == 4) ? 0 : f + 1;

    if (ty < HSq - 2) {
        int j = ty + 1;
        if (c >= 2 && c <= Sq - 4) {
            // pure inner, 2 aligned columns [c, c+1]
            const int WP = (HSq - 2) * (Sq - 2);
            int kw = (j - 1) * (Sq - 2) + (c - 1);
            float w00 = wi[kw],          w01 = wi[kw + 1];
            float w10 = wi[WP + kw],     w11 = wi[WP + kw + 1];
            float w20 = wi[2 * WP + kw], w21 = wi[2 * WP + kw + 1];
            float w30 = wi[3 * WP + kw], w31 = wi[3 * WP + kw + 1];
            float w40 = wi[4 * WP + kw], w41 = wi[4 * WP + kw + 1];
            float w50 = wi[5 * WP + kw], w51 = wi[5 * WP + kw + 1];

            const float* xp = x + (size_t)f * FP + (size_t)j * Sq;
            float* ob = out + (size_t)f * FP + (size_t)j * Sq + c;

            #pragma unroll 1
            for (int b = 0; b < Bq; b++) {
                const float* rowc = xp;
                const float* rowm = xp - Sq;
                const float* rowp = xp + Sq;
                float2 rm = *(const float2*)(rowm + c);
                float2 rc = *(const float2*)(rowc + c);
                float2 rp = *(const float2*)(rowp + c);
                float smm = rowm[c - 1];
                float sm  = rowc[c - 1];
                float sp  = rowc[c + 2];
                float spp = rowp[c + 2];

                // lane 0: ctr = rc.x ; lane 1: ctr = rc.y
                float2 o0 = make_float2((smm  - rc.x) * w00, (rm.x - rc.y) * w01);
                float2 o1 = make_float2((rp.y - rc.x) * w10, (spp  - rc.y) * w11);
                float2 o2 = make_float2((rm.x - rc.x) * w20 + (rc.y - rc.x) * w30,
                                        (rm.y - rc.y) * w21 + (sp   - rc.y) * w31);
                float2 o3 = make_float2((sm   - rc.x) * w40 + (rp.x - rc.x) * w50,
                                        (rc.x - rc.y) * w41 + (rp.y - rc.y) * w51);

                __stcs((float2*)ob,             o0);
                __stcs((float2*)(ob + CP5),     o1);
                __stcs((float2*)(ob + 2 * CP5), o2);
                __stcs((float2*)(ob + 3 * CP5), o3);

                xp += NF * FP;
                ob += 20 * FP;
            }
        } else {
            // edge chunk: contains col 0 (c==0) or col S-1 (c==S-2)
            #pragma unroll 1
            for (int b = 0; b < Bq; b++) {
                const float* xb = x + (size_t)b * NF * FP;
                const float* xp = xb + (size_t)f * FP;
                float t0[2], t1[2], t2[2], t3[2];
                #pragma unroll
                for (int l = 0; l < 2; l++) {
                    int i = c + l;
                    if (i == 0 || i == Sq - 1)
                        bpoint(xb, poles, we, wcn, wne, wnne, wnw, wnww,
                               wwe, wsw, wsse, wse, wcs,
                               b, f, pf, nf2, j, i, t0[l], t1[l], t2[l], t3[l]);
                    else
                        ipoint(xp, wi, j, i, t0[l], t1[l], t2[l], t3[l]);
                }
                size_t base = (size_t)(b * 20 + f) * FP + (size_t)j * Sq + c;
                __stcs((float2*)(out + base),           make_float2(t0[0], t0[1]));
                __stcs((float2*)(out + base + CP5),     make_float2(t1[0], t1[1]));
                __stcs((float2*)(out + base + 2 * CP5), make_float2(t2[0], t2[1]));
                __stcs((float2*)(out + base + 3 * CP5), make_float2(t3[0], t3[1]));
            }
        }
    } else {
        // boundary rows j=0 / j=HS-1: one block-row per (row, b); f from grid
        int q   = ty - (HSq - 2);            // 0..(2*Bq-1)
        int row = (q < Bq) ? 0 : (HSq - 1);
        int b   = (q < Bq) ? q : q - Bq;
        const float* xb = x + (size_t)b * NF * FP;

        float t0[2], t1[2], t2[2], t3[2];
        #pragma unroll
        for (int l = 0; l < 2; l++) {
            bpoint(xb, poles, we, wcn, wne, wnne, wnw, wnww,
                   wwe, wsw, wsse, wse, wcs,
                   b, f, pf, nf2, row, c + l, t0[l], t1[l], t2[l], t3[l]);
        }
        size_t base = (size_t)(b * 20 + f) * FP + (size_t)row * Sq + c;
        __stcs((float2*)(out + base),           make_float2(t0[0], t0[1]));
        __stcs((float2*)(out + base + CP5),     make_float2(t1[0], t1[1]));
        __stcs((float2*)(out + base + 2 * CP5), make_float2(t2[0], t2[1]));
        __stcs((float2*)(out + base + 3 * CP5), make_float2(t3[0], t3[1]));
    }
}

extern "C" void kernel_launch(void* const* d_in, const int* in_sizes, int n_in,
                              void* d_out, int out_size)
{
    const float* x     = (const float*)d_in[0];
    const float* poles = (const float*)d_in[1];
    const float* wi    = (const float*)d_in[2];
    const float* we    = (const float*)d_in[3];
    const float* wcn   = (const float*)d_in[4];
    const float* wne   = (const float*)d_in[5];
    const float* wnne  = (const float*)d_in[6];
    const float* wnw   = (const float*)d_in[7];
    const float* wnww  = (const float*)d_in[8];
    const float* wwe   = (const float*)d_in[9];
    const float* wsw   = (const float*)d_in[10];
    const float* wsse  = (const float*)d_in[11];
    const float* wse   = (const float*)d_in[12];
    const float* wcs   = (const float*)d_in[13];
    float* out = (float*)d_out;

    // grid.x: 1024 cols / (2 per thread * 128 threads) = 4
    // grid.y: 510 interior rows + 2*Bq boundary-row rows; grid.z: faces
    dim3 block(128, 1, 1);
    dim3 grid(Sq / (2 * 128), (HSq - 2) + 2 * Bq, NF);
    fused_kernel<<<grid, block>>>(x, poles, wi, we, wcn, wne, wnne, wnw, wnww,
                                  wwe, wsw, wsse, wse, wcs, out);
}

// round 5
// speedup vs baseline: 1.0232x; 1.0232x over previous
#include <cuda_runtime.h>
#include <cuda_bf16.h>
#include <cstdint>

#define Bq 4
#define NF 5
#define HSq 512
#define Sq 1024

#define XF(ff,jj,ii) xb[((size_t)(ff)*HSq + (jj))*Sq + (ii)]

// Boundary point: ports the reference's 12 perimeter cases for one (j,i).
__device__ __forceinline__ void bpoint(
    const float* __restrict__ xb, const float* __restrict__ poles,
    const float* __restrict__ we,   const float* __restrict__ wcn,
    const float* __restrict__ wne,  const float* __restrict__ wnne,
    const float* __restrict__ wnw,  const float* __restrict__ wnww,
    const float* __restrict__ wwe,  const float* __restrict__ wsw,
    const float* __restrict__ wsse, const float* __restrict__ wse,
    const float* __restrict__ wcs,
    int b, int f, int pf, int nf2, int j, int i,
    float& c0, float& c1, float& c2, float& c3)
{
    if (j == 0) {
        float ctr = XF(f, 0, i);
        if (i == 0) {
            c0 = (XF(pf, HSq - 1, HSq - 1) - ctr) * wcs[0];
            c1 = (XF(f, 1, 1) - ctr) * wcs[1];
            c2 = (XF(pf, HSq - 1, HSq) - ctr) * wcs[2] + (XF(f, 0, 1) - ctr) * wcs[3];
            c3 = (XF(f, 1, 0) - ctr) * wcs[4];
        } else if (i <= HSq - 1) {
            int k = i - 1; const int W = HSq - 1;
            c0 = (XF(pf, HSq - 1, HSq + k) - ctr) * we[k];
            c1 = (XF(f, 1, i + 1) - ctr) * we[W + k];
            c2 = (XF(pf, HSq - 1, HSq + 1 + k) - ctr) * we[2 * W + k]
               + (XF(f, 0, i + 1) - ctr) * we[3 * W + k];
            c3 = (XF(f, 0, i - 1) - ctr) * we[4 * W + k]
               + (XF(f, 1, i) - ctr) * we[5 * W + k];
        } else if (i == HSq) {
            c0 = (XF(pf, HSq - 1, Sq - 1) - ctr) * wcn[0];
            c1 = (XF(f, 1, HSq + 1) - ctr) * wcn[1];
            c2 = (XF(f, 0, HSq + 1) - ctr) * wcn[2];
            c3 = (XF(f, 0, HSq - 1) - ctr) * wcn[3] + (XF(f, 1, HSq) - ctr) * wcn[4];
        } else if (i <= Sq - 2) {
            int k = i - (HSq + 1); const int W = HSq - 2;
            c0 = (XF(pf, HSq - 2 - k, Sq - 1) - ctr) * wne[k]
               + (XF(pf, HSq - 1 - k, Sq - 1) - ctr) * wne[W + k];
            c1 = (XF(f, 1, i + 1) - ctr) * wne[2 * W + k]
               + (XF(f, 1, i) - ctr) * wne[3 * W + k];
            c2 = (XF(f, 0, i + 1) - ctr) * wne[4 * W + k];
            c3 = (XF(f, 0, i - 1) - ctr) * wne[5 * W + k];
        } else {
            c0 = (XF(pf, 0, Sq - 1) - ctr) * wnne[0] + (XF(pf, 1, Sq - 1) - ctr) * wnne[1];
            c1 = (XF(nf2, 0, Sq - 1) - ctr) * wnne[2] + (XF(f, 1, Sq - 1) - ctr) * wnne[3];
            c2 = (poles[b * 2 + 1] - ctr) * wnne[4];
            c3 = (XF(f, 0, Sq - 2) - ctr) * wnne[5];
        }
    } else if (j == HSq - 1) {
        float ctr = XF(f, HSq - 1, i);
        if (i == 0) {
            c0 = (XF(pf, HSq - 1, 0) - ctr) * wsse[0];
            c1 = (XF(nf2, HSq - 1, 0) - ctr) * wsse[1];
            c2 = (XF(f, HSq - 2, 0) - ctr) * wsse[2] + (XF(f, HSq - 1, 1) - ctr) * wsse[3];
            c3 = (poles[b * 2 + 0] - ctr) * wsse[4];
        } else if (i <= HSq - 1) {
            int k = i - 1; const int W = HSq - 1;
            c0 = (XF(f, HSq - 2, i - 1) - ctr) * wsw[k];
            c1 = (XF(nf2, HSq - 2 - k, 0) - ctr) * wsw[W + k];
            c2 = (XF(f, HSq - 2, i) - ctr) * wsw[2 * W + k]
               + (XF(f, HSq - 1, i + 1) - ctr) * wsw[3 * W + k];
            c3 = (XF(f, HSq - 1, i - 1) - ctr) * wsw[4 * W + k]
               + (XF(nf2, HSq - 1 - k, 0) - ctr) * wsw[5 * W + k];
        } else if (i <= Sq - 2) {
            int k = i - HSq; const int W = HSq - 1;
            c0 = (XF(f, HSq - 2, i - 1) - ctr) * wwe[k];
            c1 = (XF(nf2, 0, 1 + k) - ctr) * wwe[W + k];
            c2 = (XF(f, HSq - 2, i) - ctr) * wwe[2 * W + k]
               + (XF(f, HSq - 1, i + 1) - ctr) * wwe[3 * W + k];
            c3 = (XF(f, HSq - 1, i - 1) - ctr) * wwe[4 * W + k]
               + (XF(nf2, 0, k) - ctr) * wwe[5 * W + k];
        } else {
            c0 = (XF(f, HSq - 2, Sq - 2) - ctr) * wnww[0];
            c1 = (XF(nf2, 0, HSq) - ctr) * wnww[1];
            c2 = (XF(f, HSq - 2, Sq - 1) - ctr) * wnww[2]
               + (XF(nf2, 0, HSq + 1) - ctr) * wnww[3];
            c3 = (XF(f, HSq - 1, Sq - 2) - ctr) * wnww[4]
               + (XF(nf2, 0, HSq - 1) - ctr) * wnww[5];
        }
    } else if (i == 0) {
        int k = j - 1; const int W = HSq - 2;
        float ctr = XF(f, j, 0);
        c0 = (XF(pf, HSq - 1, HSq - 1 - k) - ctr) * wse[k]
           + (XF(pf, HSq - 1, HSq - 2 - k) - ctr) * wse[W + k];
        c1 = (XF(f, j, 1) - ctr) * wse[2 * W + k]
           + (XF(f, j + 1, 1) - ctr) * wse[3 * W + k];
        c2 = (XF(f, j - 1, 0) - ctr) * wse[4 * W + k];
        c3 = (XF(f, j + 1, 0) - ctr) * wse[5 * W + k];
    } else {
        int k = j - 1; const int W = HSq - 2;
        float ctr = XF(f, j, Sq - 1);
        c0 = (XF(f, j - 1, Sq - 2) - ctr) * wnw[k];
        c1 = (XF(nf2, 0, Sq - 2 - k) - ctr) * wnw[W + k];
        c2 = (XF(f, j - 1, Sq - 1) - ctr) * wnw[2 * W + k]
           + (XF(nf2, 0, Sq - 1 - k) - ctr) * wnw[3 * W + k];
        c3 = (XF(f, j, Sq - 2) - ctr) * wnw[4 * W + k]
           + (XF(f, j + 1, Sq - 1) - ctr) * wnw[5 * W + k];
    }
}

// Inner scalar point
__device__ __forceinline__ void ipoint(
    const float* __restrict__ xp, const float* __restrict__ wi,
    int j, int i, float& c0, float& c1, float& c2, float& c3)
{
    const int WP = (HSq - 2) * (Sq - 2);
    int k = (j - 1) * (Sq - 2) + (i - 1);
    float ctr = xp[(size_t)j * Sq + i];
    c0 = (xp[(size_t)(j - 1) * Sq + i - 1] - ctr) * wi[k];
    c1 = (xp[(size_t)(j + 1) * Sq + i + 1] - ctr) * wi[WP + k];
    c2 = (xp[(size_t)(j - 1) * Sq + i] - ctr) * wi[2 * WP + k]
       + (xp[(size_t)j * Sq + i + 1] - ctr) * wi[3 * WP + k];
    c3 = (xp[(size_t)j * Sq + i - 1] - ctr) * wi[4 * WP + k]
       + (xp[(size_t)(j + 1) * Sq + i] - ctr) * wi[5 * WP + k];
}

__global__ void __launch_bounds__(128) fused_kernel(
    const float* __restrict__ x,
    const float* __restrict__ poles,
    const float* __restrict__ wi,
    const float* __restrict__ we,   const float* __restrict__ wcn,
    const float* __restrict__ wne,  const float* __restrict__ wnne,
    const float* __restrict__ wnw,  const float* __restrict__ wnww,
    const float* __restrict__ wwe,  const float* __restrict__ wsw,
    const float* __restrict__ wsse, const float* __restrict__ wse,
    const float* __restrict__ wcs,
    float* __restrict__ out)
{
    const size_t FP  = (size_t)HSq * Sq;     // one face plane
    const size_t CP5 = (size_t)NF * FP;      // comp stride in out

    int c  = 2 * (blockIdx.x * 128 + threadIdx.x);   // 2 columns per thread
    int ty = blockIdx.y;
    int f  = blockIdx.z;
    int pf  = (f == 0) ? 4 : f - 1;
    int nf2 = (f == 4) ? 0 : f + 1;

    if (ty < HSq - 2) {
        int j = ty + 1;
        if (c >= 2 && c <= Sq - 4) {
            // pure inner, 2 aligned columns [c, c+1], software-pipelined b-loop
            const int WP = (HSq - 2) * (Sq - 2);
            int kw = (j - 1) * (Sq - 2) + (c - 1);
            float w00 = wi[kw],          w01 = wi[kw + 1];
            float w10 = wi[WP + kw],     w11 = wi[WP + kw + 1];
            float w20 = wi[2 * WP + kw], w21 = wi[2 * WP + kw + 1];
            float w30 = wi[3 * WP + kw], w31 = wi[3 * WP + kw + 1];
            float w40 = wi[4 * WP + kw], w41 = wi[4 * WP + kw + 1];
            float w50 = wi[5 * WP + kw], w51 = wi[5 * WP + kw + 1];

            const float* xp = x + (size_t)f * FP + (size_t)j * Sq;
            float* ob = out + (size_t)f * FP + (size_t)j * Sq + c;

            // prologue: prefetch b = 0
            float2 rm = *(const float2*)(xp - Sq + c);
            float2 rc = *(const float2*)(xp + c);
            float2 rp = *(const float2*)(xp + Sq + c);
            float smm = xp[-Sq + c - 1];
            float sm  = xp[c - 1];
            float sp  = xp[c + 2];
            float spp = xp[Sq + c + 2];

            #pragma unroll
            for (int b = 0; b < Bq; b++) {
                // snapshot current iteration's operands
                float2 crm = rm, crc = rc, crp = rp;
                float csmm = smm, csm = sm, csp = sp, cspp = spp;

                // prefetch next b while current computes/stores
                if (b + 1 < Bq) {
                    const float* xn = xp + (size_t)NF * FP;
                    rm  = *(const float2*)(xn - Sq + c);
                    rc  = *(const float2*)(xn + c);
                    rp  = *(const float2*)(xn + Sq + c);
                    smm = xn[-Sq + c - 1];
                    sm  = xn[c - 1];
                    sp  = xn[c + 2];
                    spp = xn[Sq + c + 2];
                    xp  = xn;
                }

                // lane 0: ctr = crc.x ; lane 1: ctr = crc.y
                float2 o0 = make_float2((csmm  - crc.x) * w00, (crm.x - crc.y) * w01);
                float2 o1 = make_float2((crp.y - crc.x) * w10, (cspp  - crc.y) * w11);
                float2 o2 = make_float2((crm.x - crc.x) * w20 + (crc.y - crc.x) * w30,
                                        (crm.y - crc.y) * w21 + (csp   - crc.y) * w31);
                float2 o3 = make_float2((csm   - crc.x) * w40 + (crp.x - crc.x) * w50,
                                        (crc.x - crc.y) * w41 + (crp.y - crc.y) * w51);

                __stcs((float2*)ob,             o0);
                __stcs((float2*)(ob + CP5),     o1);
                __stcs((float2*)(ob + 2 * CP5), o2);
                __stcs((float2*)(ob + 3 * CP5), o3);

                ob += 20 * FP;
            }
        } else {
            // edge chunk: contains col 0 (c==0) or col S-1 (c==S-2)
            #pragma unroll 1
            for (int b = 0; b < Bq; b++) {
                const float* xb = x + (size_t)b * NF * FP;
                const float* xp = xb + (size_t)f * FP;
                float t0[2], t1[2], t2[2], t3[2];
                #pragma unroll
                for (int l = 0; l < 2; l++) {
                    int i = c + l;
                    if (i == 0 || i == Sq - 1)
                        bpoint(xb, poles, we, wcn, wne, wnne, wnw, wnww,
                               wwe, wsw, wsse, wse, wcs,
                               b, f, pf, nf2, j, i, t0[l], t1[l], t2[l], t3[l]);
                    else
                        ipoint(xp, wi, j, i, t0[l], t1[l], t2[l], t3[l]);
                }
                size_t base = (size_t)(b * 20 + f) * FP + (size_t)j * Sq + c;
                __stcs((float2*)(out + base),           make_float2(t0[0], t0[1]));
                __stcs((float2*)(out + base + CP5),     make_float2(t1[0], t1[1]));
                __stcs((float2*)(out + base + 2 * CP5), make_float2(t2[0], t2[1]));
                __stcs((float2*)(out + base + 3 * CP5), make_float2(t3[0], t3[1]));
            }
        }
    } else {
        // boundary rows j=0 / j=HS-1: one block-row per (row, b); f from grid
        int q   = ty - (HSq - 2);            // 0..(2*Bq-1)
        int row = (q < Bq) ? 0 : (HSq - 1);
        int b   = (q < Bq) ? q : q - Bq;
        const float* xb = x + (size_t)b * NF * FP;

        float t0[2], t1[2], t2[2], t3[2];
        #pragma unroll
        for (int l = 0; l < 2; l++) {
            bpoint(xb, poles, we, wcn, wne, wnne, wnw, wnww,
                   wwe, wsw, wsse, wse, wcs,
                   b, f, pf, nf2, row, c + l, t0[l], t1[l], t2[l], t3[l]);
        }
        size_t base = (size_t)(b * 20 + f) * FP + (size_t)row * Sq + c;
        __stcs((float2*)(out + base),           make_float2(t0[0], t0[1]));
        __stcs((float2*)(out + base + CP5),     make_float2(t1[0], t1[1]));
        __stcs((float2*)(out + base + 2 * CP5), make_float2(t2[0], t2[1]));
        __stcs((float2*)(out + base + 3 * CP5), make_float2(t3[0], t3[1]));
    }
}

extern "C" void kernel_launch(void* const* d_in, const int* in_sizes, int n_in,
                              void* d_out, int out_size)
{
    const float* x     = (const float*)d_in[0];
    const float* poles = (const float*)d_in[1];
    const float* wi    = (const float*)d_in[2];
    const float* we    = (const float*)d_in[3];
    const float* wcn   = (const float*)d_in[4];
    const float* wne   = (const float*)d_in[5];
    const float* wnne  = (const float*)d_in[6];
    const float* wnw   = (const float*)d_in[7];
    const float* wnww  = (const float*)d_in[8];
    const float* wwe   = (const float*)d_in[9];
    const float* wsw   = (const float*)d_in[10];
    const float* wsse  = (const float*)d_in[11];
    const float* wse   = (const float*)d_in[12];
    const float* wcs   = (const float*)d_in[13];
    float* out = (float*)d_out;

    dim3 block(128, 1, 1);
    dim3 grid(Sq / (2 * 128), (HSq - 2) + 2 * Bq, NF);
    fused_kernel<<<grid, block>>>(x, poles, wi, we, wcn, wne, wnne, wnw, wnww,
                                  wwe, wsw, wsse, wse, wcs, out);
}

// round 6
// speedup vs baseline: 1.0315x; 1.0080x over previous
#include <cuda_runtime.h>
#include <cuda_bf16.h>
#include <cstdint>

#define Bq 4
#define NF 5
#define HSq 512
#define Sq 1024

#define XF(ff,jj,ii) xb[((size_t)(ff)*HSq + (jj))*Sq + (ii)]

// Boundary point: ports the reference's 12 perimeter cases for one (j,i).
__device__ __forceinline__ void bpoint(
    const float* __restrict__ xb, const float* __restrict__ poles,
    const float* __restrict__ we,   const float* __restrict__ wcn,
    const float* __restrict__ wne,  const float* __restrict__ wnne,
    const float* __restrict__ wnw,  const float* __restrict__ wnww,
    const float* __restrict__ wwe,  const float* __restrict__ wsw,
    const float* __restrict__ wsse, const float* __restrict__ wse,
    const float* __restrict__ wcs,
    int b, int f, int pf, int nf2, int j, int i,
    float& c0, float& c1, float& c2, float& c3)
{
    if (j == 0) {
        float ctr = XF(f, 0, i);
        if (i == 0) {
            c0 = (XF(pf, HSq - 1, HSq - 1) - ctr) * wcs[0];
            c1 = (XF(f, 1, 1) - ctr) * wcs[1];
            c2 = (XF(pf, HSq - 1, HSq) - ctr) * wcs[2] + (XF(f, 0, 1) - ctr) * wcs[3];
            c3 = (XF(f, 1, 0) - ctr) * wcs[4];
        } else if (i <= HSq - 1) {
            int k = i - 1; const int W = HSq - 1;
            c0 = (XF(pf, HSq - 1, HSq + k) - ctr) * we[k];
            c1 = (XF(f, 1, i + 1) - ctr) * we[W + k];
            c2 = (XF(pf, HSq - 1, HSq + 1 + k) - ctr) * we[2 * W + k]
               + (XF(f, 0, i + 1) - ctr) * we[3 * W + k];
            c3 = (XF(f, 0, i - 1) - ctr) * we[4 * W + k]
               + (XF(f, 1, i) - ctr) * we[5 * W + k];
        } else if (i == HSq) {
            c0 = (XF(pf, HSq - 1, Sq - 1) - ctr) * wcn[0];
            c1 = (XF(f, 1, HSq + 1) - ctr) * wcn[1];
            c2 = (XF(f, 0, HSq + 1) - ctr) * wcn[2];
            c3 = (XF(f, 0, HSq - 1) - ctr) * wcn[3] + (XF(f, 1, HSq) - ctr) * wcn[4];
        } else if (i <= Sq - 2) {
            int k = i - (HSq + 1); const int W = HSq - 2;
            c0 = (XF(pf, HSq - 2 - k, Sq - 1) - ctr) * wne[k]
               + (XF(pf, HSq - 1 - k, Sq - 1) - ctr) * wne[W + k];
            c1 = (XF(f, 1, i + 1) - ctr) * wne[2 * W + k]
               + (XF(f, 1, i) - ctr) * wne[3 * W + k];
            c2 = (XF(f, 0, i + 1) - ctr) * wne[4 * W + k];
            c3 = (XF(f, 0, i - 1) - ctr) * wne[5 * W + k];
        } else {
            c0 = (XF(pf, 0, Sq - 1) - ctr) * wnne[0] + (XF(pf, 1, Sq - 1) - ctr) * wnne[1];
            c1 = (XF(nf2, 0, Sq - 1) - ctr) * wnne[2] + (XF(f, 1, Sq - 1) - ctr) * wnne[3];
            c2 = (poles[b * 2 + 1] - ctr) * wnne[4];
            c3 = (XF(f, 0, Sq - 2) - ctr) * wnne[5];
        }
    } else if (j == HSq - 1) {
        float ctr = XF(f, HSq - 1, i);
        if (i == 0) {
            c0 = (XF(pf, HSq - 1, 0) - ctr) * wsse[0];
            c1 = (XF(nf2, HSq - 1, 0) - ctr) * wsse[1];
            c2 = (XF(f, HSq - 2, 0) - ctr) * wsse[2] + (XF(f, HSq - 1, 1) - ctr) * wsse[3];
            c3 = (poles[b * 2 + 0] - ctr) * wsse[4];
        } else if (i <= HSq - 1) {
            int k = i - 1; const int W = HSq - 1;
            c0 = (XF(f, HSq - 2, i - 1) - ctr) * wsw[k];
            c1 = (XF(nf2, HSq - 2 - k, 0) - ctr) * wsw[W + k];
            c2 = (XF(f, HSq - 2, i) - ctr) * wsw[2 * W + k]
               + (XF(f, HSq - 1, i + 1) - ctr) * wsw[3 * W + k];
            c3 = (XF(f, HSq - 1, i - 1) - ctr) * wsw[4 * W + k]
               + (XF(nf2, HSq - 1 - k, 0) - ctr) * wsw[5 * W + k];
        } else if (i <= Sq - 2) {
            int k = i - HSq; const int W = HSq - 1;
            c0 = (XF(f, HSq - 2, i - 1) - ctr) * wwe[k];
            c1 = (XF(nf2, 0, 1 + k) - ctr) * wwe[W + k];
            c2 = (XF(f, HSq - 2, i) - ctr) * wwe[2 * W + k]
               + (XF(f, HSq - 1, i + 1) - ctr) * wwe[3 * W + k];
            c3 = (XF(f, HSq - 1, i - 1) - ctr) * wwe[4 * W + k]
               + (XF(nf2, 0, k) - ctr) * wwe[5 * W + k];
        } else {
            c0 = (XF(f, HSq - 2, Sq - 2) - ctr) * wnww[0];
            c1 = (XF(nf2, 0, HSq) - ctr) * wnww[1];
            c2 = (XF(f, HSq - 2, Sq - 1) - ctr) * wnww[2]
               + (XF(nf2, 0, HSq + 1) - ctr) * wnww[3];
            c3 = (XF(f, HSq - 1, Sq - 2) - ctr) * wnww[4]
               + (XF(nf2, 0, HSq - 1) - ctr) * wnww[5];
        }
    } else if (i == 0) {
        int k = j - 1; const int W = HSq - 2;
        float ctr = XF(f, j, 0);
        c0 = (XF(pf, HSq - 1, HSq - 1 - k) - ctr) * wse[k]
           + (XF(pf, HSq - 1, HSq - 2 - k) - ctr) * wse[W + k];
        c1 = (XF(f, j, 1) - ctr) * wse[2 * W + k]
           + (XF(f, j + 1, 1) - ctr) * wse[3 * W + k];
        c2 = (XF(f, j - 1, 0) - ctr) * wse[4 * W + k];
        c3 = (XF(f, j + 1, 0) - ctr) * wse[5 * W + k];
    } else {
        int k = j - 1; const int W = HSq - 2;
        float ctr = XF(f, j, Sq - 1);
        c0 = (XF(f, j - 1, Sq - 2) - ctr) * wnw[k];
        c1 = (XF(nf2, 0, Sq - 2 - k) - ctr) * wnw[W + k];
        c2 = (XF(f, j - 1, Sq - 1) - ctr) * wnw[2 * W + k]
           + (XF(nf2, 0, Sq - 1 - k) - ctr) * wnw[3 * W + k];
        c3 = (XF(f, j, Sq - 2) - ctr) * wnw[4 * W + k]
           + (XF(f, j + 1, Sq - 1) - ctr) * wnw[5 * W + k];
    }
}

// Inner scalar point
__device__ __forceinline__ void ipoint(
    const float* __restrict__ xp, const float* __restrict__ wi,
    int j, int i, float& c0, float& c1, float& c2, float& c3)
{
    const int WP = (HSq - 2) * (Sq - 2);
    int k = (j - 1) * (Sq - 2) + (i - 1);
    float ctr = xp[(size_t)j * Sq + i];
    c0 = (xp[(size_t)(j - 1) * Sq + i - 1] - ctr) * wi[k];
    c1 = (xp[(size_t)(j + 1) * Sq + i + 1] - ctr) * wi[WP + k];
    c2 = (xp[(size_t)(j - 1) * Sq + i] - ctr) * wi[2 * WP + k]
       + (xp[(size_t)j * Sq + i + 1] - ctr) * wi[3 * WP + k];
    c3 = (xp[(size_t)j * Sq + i - 1] - ctr) * wi[4 * WP + k]
       + (xp[(size_t)(j + 1) * Sq + i] - ctr) * wi[5 * WP + k];
}

__global__ void __launch_bounds__(128) fused_kernel(
    const float* __restrict__ x,
    const float* __restrict__ poles,
    const float* __restrict__ wi,
    const float* __restrict__ we,   const float* __restrict__ wcn,
    const float* __restrict__ wne,  const float* __restrict__ wnne,
    const float* __restrict__ wnw,  const float* __restrict__ wnww,
    const float* __restrict__ wwe,  const float* __restrict__ wsw,
    const float* __restrict__ wsse, const float* __restrict__ wse,
    const float* __restrict__ wcs,
    float* __restrict__ out)
{
    const size_t FP  = (size_t)HSq * Sq;     // one face plane
    const size_t CP5 = (size_t)NF * FP;      // comp stride in out
    const unsigned FULL = 0xffffffffu;

    int tx = threadIdx.x;
    int c  = 4 * (blockIdx.x * 128 + tx);    // 4 columns per thread
    int ty = blockIdx.y;
    int f  = blockIdx.z;
    int pf  = (f == 0) ? 4 : f - 1;
    int nf2 = (f == 4) ? 0 : f + 1;

    if (ty < HSq - 2) {
        int j = ty + 1;
        int lane = tx & 31;
        bool pure = (c >= 4 && c <= Sq - 8);
        bool lo = (lane == 0)  && (c != 0);        // needs scalar c-1 halo
        bool hi = (lane == 31) && (c != Sq - 4);   // needs scalar c+4 halo

        // weights (only valid/used for pure threads)
        float w0[4], w1[4], w2[4], w3[4], w4[4], w5[4];
        if (pure) {
            const int WP = (HSq - 2) * (Sq - 2);
            int kw = (j - 1) * (Sq - 2) + (c - 1);
            #pragma unroll
            for (int l = 0; l < 4; l++) {
                w0[l] = wi[kw + l];
                w1[l] = wi[WP + kw + l];
                w2[l] = wi[2 * WP + kw + l];
                w3[l] = wi[3 * WP + kw + l];
                w4[l] = wi[4 * WP + kw + l];
                w5[l] = wi[5 * WP + kw + l];
            }
        }

        const float* xp = x + (size_t)f * FP + (size_t)j * Sq;
        float* ob = out + (size_t)f * FP + (size_t)j * Sq + c;

        // prologue: prefetch b = 0 (ALL threads, incl. edge threads, for shfl)
        float4 rm = *(const float4*)(xp - Sq + c);
        float4 rc = *(const float4*)(xp + c);
        float4 rp = *(const float4*)(xp + Sq + c);
        float hsmm = lo ? xp[-Sq + c - 1] : 0.0f;
        float hsm  = lo ? xp[c - 1]       : 0.0f;
        float hsp  = hi ? xp[c + 4]       : 0.0f;
        float hspp = hi ? xp[Sq + c + 4]  : 0.0f;

        #pragma unroll
        for (int b = 0; b < Bq; b++) {
            float4 crm = rm, crc = rc, crp = rp;
            float chsmm = hsmm, chsm = hsm, chsp = hsp, chspp = hspp;

            if (b + 1 < Bq) {
                const float* xn = xp + (size_t)NF * FP;
                rm = *(const float4*)(xn - Sq + c);
                rc = *(const float4*)(xn + c);
                rp = *(const float4*)(xn + Sq + c);
                hsmm = lo ? xn[-Sq + c - 1] : 0.0f;
                hsm  = lo ? xn[c - 1]       : 0.0f;
                hsp  = hi ? xn[c + 4]       : 0.0f;
                hspp = hi ? xn[Sq + c + 4]  : 0.0f;
                xp = xn;
            }

            // halo exchange via shuffle (uniform across the warp)
            float smm = __shfl_up_sync(FULL, crm.w, 1);
            float sm  = __shfl_up_sync(FULL, crc.w, 1);
            float sp  = __shfl_down_sync(FULL, crc.x, 1);
            float spp = __shfl_down_sync(FULL, crp.x, 1);
            if (lo) { smm = chsmm; sm = chsm; }
            if (hi) { sp  = chsp;  spp = chspp; }

            if (pure) {
                float A[5]  = {smm, crm.x, crm.y, crm.z, crm.w};
                float Bv[6] = {sm,  crc.x, crc.y, crc.z, crc.w, sp};
                float Cv[5] = {crp.x, crp.y, crp.z, crp.w, spp};

                float4 o;
                o.x = (A[0] - Bv[1]) * w0[0];
                o.y = (A[1] - Bv[2]) * w0[1];
                o.z = (A[2] - Bv[3]) * w0[2];
                o.w = (A[3] - Bv[4]) * w0[3];
                __stcs((float4*)ob, o);
                o.x = (Cv[1] - Bv[1]) * w1[0];
                o.y = (Cv[2] - Bv[2]) * w1[1];
                o.z = (Cv[3] - Bv[3]) * w1[2];
                o.w = (Cv[4] - Bv[4]) * w1[3];
                __stcs((float4*)(ob + CP5), o);
                o.x = (A[1] - Bv[1]) * w2[0] + (Bv[2] - Bv[1]) * w3[0];
                o.y = (A[2] - Bv[2]) * w2[1] + (Bv[3] - Bv[2]) * w3[1];
                o.z = (A[3] - Bv[3]) * w2[2] + (Bv[4] - Bv[3]) * w3[2];
                o.w = (A[4] - Bv[4]) * w2[3] + (Bv[5] - Bv[4]) * w3[3];
                __stcs((float4*)(ob + 2 * CP5), o);
                o.x = (Bv[0] - Bv[1]) * w4[0] + (Cv[0] - Bv[1]) * w5[0];
                o.y = (Bv[1] - Bv[2]) * w4[1] + (Cv[1] - Bv[2]) * w5[1];
                o.z = (Bv[2] - Bv[3]) * w4[2] + (Cv[2] - Bv[3]) * w5[2];
                o.w = (Bv[3] - Bv[4]) * w4[3] + (Cv[3] - Bv[4]) * w5[3];
                __stcs((float4*)(ob + 3 * CP5), o);
            } else {
                // edge chunk: contains col 0 (c==0) or col S-1 (c==S-4)
                const float* xb2 = x + (size_t)b * NF * FP;
                const float* xpf = xb2 + (size_t)f * FP;
                float t0[4], t1[4], t2[4], t3[4];
                #pragma unroll
                for (int l = 0; l < 4; l++) {
                    int i = c + l;
                    if (i == 0 || i == Sq - 1)
                        bpoint(xb2, poles, we, wcn, wne, wnne, wnw, wnww,
                               wwe, wsw, wsse, wse, wcs,
                               b, f, pf, nf2, j, i, t0[l], t1[l], t2[l], t3[l]);
                    else
                        ipoint(xpf, wi, j, i, t0[l], t1[l], t2[l], t3[l]);
                }
                __stcs((float4*)ob,             make_float4(t0[0], t0[1], t0[2], t0[3]));
                __stcs((float4*)(ob + CP5),     make_float4(t1[0], t1[1], t1[2], t1[3]));
                __stcs((float4*)(ob + 2 * CP5), make_float4(t2[0], t2[1], t2[2], t2[3]));
                __stcs((float4*)(ob + 3 * CP5), make_float4(t3[0], t3[1], t3[2], t3[3]));
            }
            ob += 20 * FP;
        }
    } else {
        // boundary rows j=0 / j=HS-1: one block-row per (row, b); f from grid
        int q   = ty - (HSq - 2);            // 0..(2*Bq-1)
        int row = (q < Bq) ? 0 : (HSq - 1);
        int b   = (q < Bq) ? q : q - Bq;
        const float* xb = x + (size_t)b * NF * FP;

        float t0[4], t1[4], t2[4], t3[4];
        #pragma unroll
        for (int l = 0; l < 4; l++) {
            bpoint(xb, poles, we, wcn, wne, wnne, wnw, wnww,
                   wwe, wsw, wsse, wse, wcs,
                   b, f, pf, nf2, row, c + l, t0[l], t1[l], t2[l], t3[l]);
        }
        size_t base = (size_t)(b * 20 + f) * FP + (size_t)row * Sq + c;
        __stcs((float4*)(out + base),           make_float4(t0[0], t0[1], t0[2], t0[3]));
        __stcs((float4*)(out + base + CP5),     make_float4(t1[0], t1[1], t1[2], t1[3]));
        __stcs((float4*)(out + base + 2 * CP5), make_float4(t2[0], t2[1], t2[2], t2[3]));
        __stcs((float4*)(out + base + 3 * CP5), make_float4(t3[0], t3[1], t3[2], t3[3]));
    }
}

extern "C" void kernel_launch(void* const* d_in, const int* in_sizes, int n_in,
                              void* d_out, int out_size)
{
    const float* x     = (const float*)d_in[0];
    const float* poles = (const float*)d_in[1];
    const float* wi    = (const float*)d_in[2];
    const float* we    = (const float*)d_in[3];
    const float* wcn   = (const float*)d_in[4];
    const float* wne   = (const float*)d_in[5];
    const float* wnne  = (const float*)d_in[6];
    const float* wnw   = (const float*)d_in[7];
    const float* wnww  = (const float*)d_in[8];
    const float* wwe   = (const float*)d_in[9];
    const float* wsw   = (const float*)d_in[10];
    const float* wsse  = (const float*)d_in[11];
    const float* wse   = (const float*)d_in[12];
    const float* wcs   = (const float*)d_in[13];
    float* out = (float*)d_out;

    // grid.x: 1024 cols / (4 per thread * 128 threads) = 2
    dim3 block(128, 1, 1);
    dim3 grid(Sq / (4 * 128), (HSq - 2) + 2 * Bq, NF);
    fused_kernel<<<grid, block>>>(x, poles, wi, we, wcn, wne, wnne, wnw, wnww,
                                  wwe, wsw, wsse, wse, wcs, out);
}